// round 14
// baseline (speedup 1.0000x reference)
#include <cuda_runtime.h>
#include <math.h>

#define Bb 8
#define Nn 16384
#define Dd 768
#define Rr 3
#define NEx 4
#define Hh 128
#define KBLK 64          // K1 blocks per batch
#define PLANE 16384      // floats per (b,r) plane
#define CHPLN 49152      // floats per batch (3 planes)
#define K4GRID 4734      // 4734*256 divisible by 192 -> q invariant per thread

// ---- scratch (device globals; no allocations allowed) ----
__device__ float g_xr[Bb * Rr * PLANE];        // planar (B, R, N)
__device__ float g_mixed[Bb * Rr * PLANE];     // planar (B, R, N)
__device__ float g_partial[Bb * KBLK * 8 * 3]; // per-warp partial sums of xr

// ============================================================
// K1: xr = x @ Wd + bd. Per-warp cp.async ring, DEPTH 3, issue-first,
// 3 blocks/SM (72KB dyn smem each). 24 warps/SM.
// ============================================================
__device__ __forceinline__ void k1_issue(unsigned slotbase, const float4* src, int lane) {
#pragma unroll
    for (int i = 0; i < 6; ++i) {
        asm volatile("cp.async.cg.shared.global [%0], [%1], 16;\n"
                     :: "r"(slotbase + (unsigned)(lane + 32 * i) * 16u),
                        "l"(src + lane + 32 * i));
    }
    asm volatile("cp.async.commit_group;\n");
}

struct K1Acc { float p0, p1, p2; };

__device__ __forceinline__ void k1_compute(const float* slot, int lane,
                                           const float4* w0, const float4* w1, const float4* w2,
                                           float b0, float b1, float b2,
                                           int b, int t, K1Acc& acc) {
    const float4* tb = (const float4*)slot;
    float a0 = 0.f, a1 = 0.f, a2 = 0.f;
#pragma unroll
    for (int it = 0; it < 6; ++it) {
        float4 v = tb[lane + 32 * it];
        a0 += v.x*w0[it].x + v.y*w0[it].y + v.z*w0[it].z + v.w*w0[it].w;
        a1 += v.x*w1[it].x + v.y*w1[it].y + v.z*w1[it].z + v.w*w1[it].w;
        a2 += v.x*w2[it].x + v.y*w2[it].y + v.z*w2[it].z + v.w*w2[it].w;
    }
#pragma unroll
    for (int off = 16; off; off >>= 1) {
        a0 += __shfl_xor_sync(0xffffffffu, a0, off);
        a1 += __shfl_xor_sync(0xffffffffu, a1, off);
        a2 += __shfl_xor_sync(0xffffffffu, a2, off);
    }
    if (lane == 0) {
        a0 += b0; a1 += b1; a2 += b2;
        g_xr[b * CHPLN + t]             = a0;
        g_xr[b * CHPLN + PLANE + t]     = a1;
        g_xr[b * CHPLN + 2 * PLANE + t] = a2;
        acc.p0 += a0; acc.p1 += a1; acc.p2 += a2;
    }
}

__global__ __launch_bounds__(256, 3) void k_proj_down(const float* __restrict__ x,
                                                      const float* __restrict__ Wd,
                                                      const float* __restrict__ bd) {
    extern __shared__ float sbuf[];   // 8 warps * 3 slots * 768 floats = 72KB
    const int b = blockIdx.x >> 6, blk = blockIdx.x & 63;
    const int tid = threadIdx.x, warp = tid >> 5, lane = tid & 31;

    for (int i = tid; i < Dd * Rr; i += 256) sbuf[i] = Wd[i];
    __syncthreads();
    float4 w0[6], w1[6], w2[6];
#pragma unroll
    for (int it = 0; it < 6; ++it) {
        int d = (lane + 32 * it) * 4;
        w0[it] = make_float4(sbuf[(d+0)*3+0], sbuf[(d+1)*3+0], sbuf[(d+2)*3+0], sbuf[(d+3)*3+0]);
        w1[it] = make_float4(sbuf[(d+0)*3+1], sbuf[(d+1)*3+1], sbuf[(d+2)*3+1], sbuf[(d+3)*3+1]);
        w2[it] = make_float4(sbuf[(d+0)*3+2], sbuf[(d+1)*3+2], sbuf[(d+2)*3+2], sbuf[(d+3)*3+2]);
    }
    const float b0 = bd[0], b1 = bd[1], b2 = bd[2];
    __syncthreads();

    const int token0 = blk * 256;
    const float4* base4 = (const float4*)x + (size_t)(b * Nn + token0 + warp) * 192;
    float* wslots = sbuf + warp * 3 * Dd;
    unsigned wbase = (unsigned)__cvta_generic_to_shared(wslots);

    // prologue: fill 2 slots
    k1_issue(wbase,          base4,        lane);
    k1_issue(wbase + 3072u,  base4 + 1536, lane);

    K1Acc acc = {0.f, 0.f, 0.f};
    // slot index cycles 0,1,2 (mod 3)
    int slot = 0;
#pragma unroll 1
    for (int g = 0; g < 30; ++g) {
        int nslot = slot + 2; if (nslot >= 3) nslot -= 3;   // slot of g+2
        k1_issue(wbase + (unsigned)nslot * 3072u,
                 base4 + (size_t)(g + 2) * 1536, lane);
        asm volatile("cp.async.wait_group 2;\n");
        k1_compute(wslots + slot * Dd, lane, w0, w1, w2, b0, b1, b2,
                   b, token0 + g * 8 + warp, acc);
        if (++slot == 3) slot = 0;
    }
    asm volatile("cp.async.wait_group 1;\n");
    k1_compute(wslots + slot * Dd, lane, w0, w1, w2, b0, b1, b2,
               b, token0 + 30 * 8 + warp, acc);
    if (++slot == 3) slot = 0;
    asm volatile("cp.async.wait_group 0;\n");
    k1_compute(wslots + slot * Dd, lane, w0, w1, w2, b0, b1, b2,
               b, token0 + 31 * 8 + warp, acc);

    if (lane == 0) {
        int pi = ((b * KBLK + blk) * 8 + warp) * 3;
        g_partial[pi] = acc.p0; g_partial[pi + 1] = acc.p1; g_partial[pi + 2] = acc.p2;
    }
}

// ============================================================
// K3: fused experts + gating. grid (4 quadrants, 24 channels) x 1024.
// (R9-proven: planar g_mixed writes)
// ============================================================
template <int SC>
__device__ __forceinline__ float up_sample_s(const float* __restrict__ L, int oi, int oj) {
    constexpr int m = 128 >> SC;
    constexpr float invf = 1.0f / (float)(1 << SC);
    float sy = (oi + 0.5f) * invf - 0.5f;
    float sx = (oj + 0.5f) * invf - 0.5f;
    int y0 = (int)floorf(sy); float fy = sy - (float)y0;
    int x0 = (int)floorf(sx); float fx = sx - (float)x0;
    int y0c = max(y0, 0), y1c = min(y0 + 1, m - 1);
    int x0c = max(x0, 0), x1c = min(x0 + 1, m - 1);
    float v00 = L[y0c * m + x0c], v01 = L[y0c * m + x1c];
    float v10 = L[y1c * m + x0c], v11 = L[y1c * m + x1c];
    return (1.f - fy) * ((1.f - fx) * v00 + fx * v01)
         +        fy  * ((1.f - fx) * v10 + fx * v11);
}

__global__ __launch_bounds__(1024) void k_experts(const float* __restrict__ dwk,
                                                  const float* __restrict__ dwb,
                                                  const float* __restrict__ noise,
                                                  const float* __restrict__ Wg,
                                                  const float* __restrict__ Wn) {
    extern __shared__ float sm[];
    float* sA = sm;            // 16384
    float* sC = sm + 16384;    // 5376
    float* sD = sm + 21760;    // 5376
    __shared__ float sred[3][512];
    __shared__ float sred2[3][64];
    __shared__ float sxa[3];
    __shared__ float sK[9];
    __shared__ float sMeta[5];
    const int q = blockIdx.x;                  // quadrant 0..3
    const int ch = blockIdx.y, b = ch / 3, r = ch - b * 3;
    const int tid = threadIdx.x;
    if (tid < 9) sK[tid] = dwk[r * 9 + tid];
    if (tid == 9) sMeta[0] = dwb[r];

    if (tid < 512) {
        int base = (b * 512 + tid) * 3;
        sred[0][tid] = g_partial[base];
        sred[1][tid] = g_partial[base + 1];
        sred[2][tid] = g_partial[base + 2];
    }
    const float4* Ap = (const float4*)(g_xr + ch * PLANE);
#pragma unroll
    for (int i = 0; i < 4; ++i) ((float4*)sA)[tid + 1024 * i] = Ap[tid + 1024 * i];
    __syncthreads();

    if (tid < 192) {
        int a = tid >> 6, i = tid & 63;
        float s = 0.f;
#pragma unroll
        for (int k = 0; k < 8; ++k) s += sred[a][i * 8 + k];
        sred2[a][i] = s;
    }
    __syncthreads();
    if (tid < 24) {
        int a = tid >> 3, i = tid & 7;
        float s = 0.f;
#pragma unroll
        for (int k = 0; k < 8; ++k) s += sred2[a][i * 8 + k];
        sred[a][i] = s;
    }
    __syncthreads();
    if (tid < 3) {
        float s = 0.f;
#pragma unroll
        for (int k = 0; k < 8; ++k) s += sred[tid][k];
        sxa[tid] = s * (1.0f / Nn);
    }
    __syncthreads();
    if (tid == 0) {
        float x0 = sxa[0], x1 = sxa[1], x2 = sxa[2];
        float hl[NEx];
#pragma unroll
        for (int e = 0; e < NEx; ++e) {
            float hg = x0 * Wg[e] + x1 * Wg[NEx + e] + x2 * Wg[2 * NEx + e];
            float z  = x0 * Wn[e] + x1 * Wn[NEx + e] + x2 * Wn[2 * NEx + e];
            float sp = fmaxf(z, 0.f) + log1pf(expf(-fabsf(z)));
            hl[e] = hg + noise[b * NEx + e] * sp;
        }
        int i1 = 0;
#pragma unroll
        for (int e = 1; e < NEx; ++e) if (hl[e] > hl[i1]) i1 = e;
        int i2 = -1;
#pragma unroll
        for (int e = 0; e < NEx; ++e) if (e != i1 && (i2 < 0 || hl[e] > hl[i2])) i2 = e;
        float e2  = expf(hl[i2] - hl[i1]);
        float inv = 1.f / (1.f + e2);
#pragma unroll
        for (int e = 0; e < NEx; ++e)
            sMeta[1 + e] = (e == i1) ? inv : ((e == i2) ? e2 * inv : 0.f);
    }

    for (int p = tid; p < 5376; p += 1024) {
        int m, off, o, f, idx;
        if (p < 4096)      { m = 64; off = 0;    o = 0; f = 2; idx = p; }
        else if (p < 5120) { m = 32; off = 4096; o = 1; f = 4; idx = p - 4096; }
        else               { m = 16; off = 5120; o = 3; f = 8; idx = p - 5120; }
        int i = idx / m, j = idx - i * m;
        const float* base = sA + (f * i + o) * 128 + (f * j + o);
        sD[off + idx] = 0.25f * (base[0] + base[1] + base[128] + base[129]);
    }
    __syncthreads();

    const float bias = sMeta[0];
    for (int p = tid; p < 5376; p += 1024) {
        int m, off, idx;
        if (p < 4096)      { m = 64; off = 0;    idx = p; }
        else if (p < 5120) { m = 32; off = 4096; idx = p - 4096; }
        else               { m = 16; off = 5120; idx = p - 5120; }
        int i = idx / m, j = idx - i * m;
        float s = bias;
        const float* Dp = sD + off;
#pragma unroll
        for (int dy = -1; dy <= 1; ++dy) {
            int ii = i + dy;
            if (ii < 0 || ii >= m) continue;
#pragma unroll
            for (int dx = -1; dx <= 1; ++dx) {
                int jj = j + dx;
                if (jj < 0 || jj >= m) continue;
                s += sK[(dy + 1) * 3 + (dx + 1)] * Dp[ii * m + jj];
            }
        }
        sC[off + idx] = s;
    }
    __syncthreads();

    const float g0 = sMeta[1], g1 = sMeta[2], g2 = sMeta[3], g3 = sMeta[4];
    float* __restrict__ M = g_mixed + ch * PLANE;
#pragma unroll
    for (int it = 0; it < 4; ++it) {
        int p = q * 4096 + tid + 1024 * it;
        int i = p >> 7, j = p & 127;
        float s = bias;
#pragma unroll
        for (int dy = -1; dy <= 1; ++dy) {
            int ii = i + dy;
            if (ii < 0 || ii > 127) continue;
#pragma unroll
            for (int dx = -1; dx <= 1; ++dx) {
                int jj = j + dx;
                if (jj < 0 || jj > 127) continue;
                s += sK[(dy + 1) * 3 + (dx + 1)] * sA[ii * 128 + jj];
            }
        }
        float acc = g0 * s;
        acc += g1 * up_sample_s<1>(sC, i, j);
        acc += g2 * up_sample_s<2>(sC + 4096, i, j);
        acc += g3 * up_sample_s<3>(sC + 5120, i, j);
        M[p] = acc;
    }
}

// ============================================================
// K4: out = x + mixed @ Wu + bu. R9-proven: register-invariant weights,
// planar scalar m-loads, unroll 4. (measured ~127us)
// ============================================================
__global__ __launch_bounds__(256) void k_proj_up(const float* __restrict__ x,
                                                 const float* __restrict__ Wu,
                                                 const float* __restrict__ bu,
                                                 float* __restrict__ out) {
    const int p0 = blockIdx.x * 256 + threadIdx.x;
    const int q  = p0 % 192;                  // fixed d-chunk for this thread
    const int d4 = q * 4;
    const float4 wu0 = __ldg((const float4*)(Wu + d4));
    const float4 wu1 = __ldg((const float4*)(Wu + Dd + d4));
    const float4 wu2 = __ldg((const float4*)(Wu + 2 * Dd + d4));
    const float4 bb  = __ldg((const float4*)(bu + d4));

    const int tkstep = (K4GRID * 256) / 192;  // 6312 tokens per iteration step
    const int ntok = Bb * Nn;
#pragma unroll 4
    for (int tk = p0 / 192; tk < ntok; tk += tkstep) {
        int b = tk >> 14;
        int t = tk & (Nn - 1);
        const float* mp = g_mixed + b * CHPLN + t;
        float m0 = __ldg(mp), m1 = __ldg(mp + PLANE), m2 = __ldg(mp + 2 * PLANE);
        int p = tk * 192 + q;
        float4 xv = ((const float4*)x)[p];
        float4 ov;
        ov.x = xv.x + bb.x + m0 * wu0.x + m1 * wu1.x + m2 * wu2.x;
        ov.y = xv.y + bb.y + m0 * wu0.y + m1 * wu1.y + m2 * wu2.y;
        ov.z = xv.z + bb.z + m0 * wu0.z + m1 * wu1.z + m2 * wu2.z;
        ov.w = xv.w + bb.w + m0 * wu0.w + m1 * wu1.w + m2 * wu2.w;
        ((float4*)out)[p] = ov;
    }
}

// ============================================================
// launch (3 launches)
// ============================================================
extern "C" void kernel_launch(void* const* d_in, const int* in_sizes, int n_in,
                              void* d_out, int out_size) {
    const float* x     = (const float*)d_in[0];
    const float* noise = (const float*)d_in[1];
    const float* Wd    = (const float*)d_in[2];
    const float* bd    = (const float*)d_in[3];
    const float* Wu    = (const float*)d_in[4];
    const float* bu    = (const float*)d_in[5];
    const float* Wg    = (const float*)d_in[6];
    const float* Wn    = (const float*)d_in[7];
    const float* dwk   = (const float*)d_in[8];
    const float* dwb   = (const float*)d_in[9];
    float* out = (float*)d_out;

    cudaFuncSetAttribute(k_proj_down, cudaFuncAttributeMaxDynamicSharedMemorySize, 73728);
    cudaFuncSetAttribute(k_experts,   cudaFuncAttributeMaxDynamicSharedMemorySize, 108544);

    k_proj_down<<<Bb * KBLK, 256, 73728>>>(x, Wd, bd);
    k_experts<<<dim3(4, 24), 1024, 108544>>>(dwk, dwb, noise, Wg, Wn);
    k_proj_up<<<K4GRID, 256>>>(x, Wu, bu, out);
}

// round 17
// speedup vs baseline: 1.6467x; 1.6467x over previous
#include <cuda_runtime.h>
#include <math.h>

#define Bb 8
#define Nn 16384
#define Dd 768
#define Rr 3
#define NEx 4
#define Hh 128
#define KBLK 64          // K1 blocks per batch
#define PLANE 16384      // floats per (b,r) plane
#define CHPLN 49152      // floats per batch (3 planes)
#define K4GRID 4734      // 4734*256 divisible by 192 -> q invariant per thread

// ---- scratch (device globals; no allocations allowed) ----
__device__ float g_xr[Bb * Rr * PLANE];        // planar (B, R, N)
__device__ float g_mixed[Bb * Rr * PLANE];     // planar (B, R, N)
__device__ float g_partial[Bb * KBLK * 8 * 3]; // per-warp partial sums of xr

// ============================================================
// K1: xr = x @ Wd + bd. Per-warp cp.async ring, DEPTH 4, issue-first,
// 2 blocks/SM, 96KB dyn smem. Power-of-2 slot masking keeps the
// 72-reg weight cache resident (regs=118). Measured 66.6us @ 77.6% DRAM.
// ============================================================
__device__ __forceinline__ void k1_issue(unsigned slotbase, const float4* src, int lane) {
#pragma unroll
    for (int i = 0; i < 6; ++i) {
        asm volatile("cp.async.cg.shared.global [%0], [%1], 16;\n"
                     :: "r"(slotbase + (unsigned)(lane + 32 * i) * 16u),
                        "l"(src + lane + 32 * i));
    }
    asm volatile("cp.async.commit_group;\n");
}

struct K1Acc { float p0, p1, p2; };

__device__ __forceinline__ void k1_compute(const float* slot, int lane,
                                           const float4* w0, const float4* w1, const float4* w2,
                                           float b0, float b1, float b2,
                                           int b, int t, K1Acc& acc) {
    const float4* tb = (const float4*)slot;
    float a0 = 0.f, a1 = 0.f, a2 = 0.f;
#pragma unroll
    for (int it = 0; it < 6; ++it) {
        float4 v = tb[lane + 32 * it];
        a0 += v.x*w0[it].x + v.y*w0[it].y + v.z*w0[it].z + v.w*w0[it].w;
        a1 += v.x*w1[it].x + v.y*w1[it].y + v.z*w1[it].z + v.w*w1[it].w;
        a2 += v.x*w2[it].x + v.y*w2[it].y + v.z*w2[it].z + v.w*w2[it].w;
    }
#pragma unroll
    for (int off = 16; off; off >>= 1) {
        a0 += __shfl_xor_sync(0xffffffffu, a0, off);
        a1 += __shfl_xor_sync(0xffffffffu, a1, off);
        a2 += __shfl_xor_sync(0xffffffffu, a2, off);
    }
    if (lane == 0) {
        a0 += b0; a1 += b1; a2 += b2;
        g_xr[b * CHPLN + t]             = a0;
        g_xr[b * CHPLN + PLANE + t]     = a1;
        g_xr[b * CHPLN + 2 * PLANE + t] = a2;
        acc.p0 += a0; acc.p1 += a1; acc.p2 += a2;
    }
}

__global__ __launch_bounds__(256, 2) void k_proj_down(const float* __restrict__ x,
                                                      const float* __restrict__ Wd,
                                                      const float* __restrict__ bd) {
    extern __shared__ float sbuf[];   // 8 * 4 * 768 floats = 96KB
    const int b = blockIdx.x >> 6, blk = blockIdx.x & 63;
    const int tid = threadIdx.x, warp = tid >> 5, lane = tid & 31;

    for (int i = tid; i < Dd * Rr; i += 256) sbuf[i] = Wd[i];
    __syncthreads();
    float4 w0[6], w1[6], w2[6];
#pragma unroll
    for (int it = 0; it < 6; ++it) {
        int d = (lane + 32 * it) * 4;
        w0[it] = make_float4(sbuf[(d+0)*3+0], sbuf[(d+1)*3+0], sbuf[(d+2)*3+0], sbuf[(d+3)*3+0]);
        w1[it] = make_float4(sbuf[(d+0)*3+1], sbuf[(d+1)*3+1], sbuf[(d+2)*3+1], sbuf[(d+3)*3+1]);
        w2[it] = make_float4(sbuf[(d+0)*3+2], sbuf[(d+1)*3+2], sbuf[(d+2)*3+2], sbuf[(d+3)*3+2]);
    }
    const float b0 = bd[0], b1 = bd[1], b2 = bd[2];
    __syncthreads();

    const int token0 = blk * 256;
    const float4* base4 = (const float4*)x + (size_t)(b * Nn + token0 + warp) * 192;
    float* wslots = sbuf + warp * 4 * Dd;
    unsigned wbase = (unsigned)__cvta_generic_to_shared(wslots);

    k1_issue(wbase,              base4,            lane);
    k1_issue(wbase + 1u * 3072u, base4 + 1536,     lane);
    k1_issue(wbase + 2u * 3072u, base4 + 2 * 1536, lane);

    K1Acc acc = {0.f, 0.f, 0.f};
#pragma unroll 1
    for (int g = 0; g < 29; ++g) {
        k1_issue(wbase + (unsigned)((g + 3) & 3) * 3072u,
                 base4 + (size_t)(g + 3) * 1536, lane);
        asm volatile("cp.async.wait_group 3;\n");
        k1_compute(wslots + (g & 3) * Dd, lane, w0, w1, w2, b0, b1, b2,
                   b, token0 + g * 8 + warp, acc);
    }
    asm volatile("cp.async.wait_group 2;\n");
    k1_compute(wslots + (29 & 3) * Dd, lane, w0, w1, w2, b0, b1, b2,
               b, token0 + 29 * 8 + warp, acc);
    asm volatile("cp.async.wait_group 1;\n");
    k1_compute(wslots + (30 & 3) * Dd, lane, w0, w1, w2, b0, b1, b2,
               b, token0 + 30 * 8 + warp, acc);
    asm volatile("cp.async.wait_group 0;\n");
    k1_compute(wslots + (31 & 3) * Dd, lane, w0, w1, w2, b0, b1, b2,
               b, token0 + 31 * 8 + warp, acc);

    if (lane == 0) {
        int pi = ((b * KBLK + blk) * 8 + warp) * 3;
        g_partial[pi] = acc.p0; g_partial[pi + 1] = acc.p1; g_partial[pi + 2] = acc.p2;
    }
}

// ============================================================
// K3: fused experts + gating. grid (4 quadrants, 24 channels) x 1024.
// ============================================================
template <int SC>
__device__ __forceinline__ float up_sample_s(const float* __restrict__ L, int oi, int oj) {
    constexpr int m = 128 >> SC;
    constexpr float invf = 1.0f / (float)(1 << SC);
    float sy = (oi + 0.5f) * invf - 0.5f;
    float sx = (oj + 0.5f) * invf - 0.5f;
    int y0 = (int)floorf(sy); float fy = sy - (float)y0;
    int x0 = (int)floorf(sx); float fx = sx - (float)x0;
    int y0c = max(y0, 0), y1c = min(y0 + 1, m - 1);
    int x0c = max(x0, 0), x1c = min(x0 + 1, m - 1);
    float v00 = L[y0c * m + x0c], v01 = L[y0c * m + x1c];
    float v10 = L[y1c * m + x0c], v11 = L[y1c * m + x1c];
    return (1.f - fy) * ((1.f - fx) * v00 + fx * v01)
         +        fy  * ((1.f - fx) * v10 + fx * v11);
}

__global__ __launch_bounds__(1024) void k_experts(const float* __restrict__ dwk,
                                                  const float* __restrict__ dwb,
                                                  const float* __restrict__ noise,
                                                  const float* __restrict__ Wg,
                                                  const float* __restrict__ Wn) {
    extern __shared__ float sm[];
    float* sA = sm;            // 16384
    float* sC = sm + 16384;    // 5376
    float* sD = sm + 21760;    // 5376
    __shared__ float sred[3][512];
    __shared__ float sred2[3][64];
    __shared__ float sxa[3];
    __shared__ float sK[9];
    __shared__ float sMeta[5];
    const int q = blockIdx.x;                  // quadrant 0..3
    const int ch = blockIdx.y, b = ch / 3, r = ch - b * 3;
    const int tid = threadIdx.x;
    if (tid < 9) sK[tid] = dwk[r * 9 + tid];
    if (tid == 9) sMeta[0] = dwb[r];

    if (tid < 512) {
        int base = (b * 512 + tid) * 3;
        sred[0][tid] = g_partial[base];
        sred[1][tid] = g_partial[base + 1];
        sred[2][tid] = g_partial[base + 2];
    }
    const float4* Ap = (const float4*)(g_xr + ch * PLANE);
#pragma unroll
    for (int i = 0; i < 4; ++i) ((float4*)sA)[tid + 1024 * i] = Ap[tid + 1024 * i];
    __syncthreads();

    if (tid < 192) {
        int a = tid >> 6, i = tid & 63;
        float s = 0.f;
#pragma unroll
        for (int k = 0; k < 8; ++k) s += sred[a][i * 8 + k];
        sred2[a][i] = s;
    }
    __syncthreads();
    if (tid < 24) {
        int a = tid >> 3, i = tid & 7;
        float s = 0.f;
#pragma unroll
        for (int k = 0; k < 8; ++k) s += sred2[a][i * 8 + k];
        sred[a][i] = s;
    }
    __syncthreads();
    if (tid < 3) {
        float s = 0.f;
#pragma unroll
        for (int k = 0; k < 8; ++k) s += sred[tid][k];
        sxa[tid] = s * (1.0f / Nn);
    }
    __syncthreads();
    if (tid == 0) {
        float x0 = sxa[0], x1 = sxa[1], x2 = sxa[2];
        float hl[NEx];
#pragma unroll
        for (int e = 0; e < NEx; ++e) {
            float hg = x0 * Wg[e] + x1 * Wg[NEx + e] + x2 * Wg[2 * NEx + e];
            float z  = x0 * Wn[e] + x1 * Wn[NEx + e] + x2 * Wn[2 * NEx + e];
            float sp = fmaxf(z, 0.f) + log1pf(expf(-fabsf(z)));
            hl[e] = hg + noise[b * NEx + e] * sp;
        }
        int i1 = 0;
#pragma unroll
        for (int e = 1; e < NEx; ++e) if (hl[e] > hl[i1]) i1 = e;
        int i2 = -1;
#pragma unroll
        for (int e = 0; e < NEx; ++e) if (e != i1 && (i2 < 0 || hl[e] > hl[i2])) i2 = e;
        float e2  = expf(hl[i2] - hl[i1]);
        float inv = 1.f / (1.f + e2);
#pragma unroll
        for (int e = 0; e < NEx; ++e)
            sMeta[1 + e] = (e == i1) ? inv : ((e == i2) ? e2 * inv : 0.f);
    }

    for (int p = tid; p < 5376; p += 1024) {
        int m, off, o, f, idx;
        if (p < 4096)      { m = 64; off = 0;    o = 0; f = 2; idx = p; }
        else if (p < 5120) { m = 32; off = 4096; o = 1; f = 4; idx = p - 4096; }
        else               { m = 16; off = 5120; o = 3; f = 8; idx = p - 5120; }
        int i = idx / m, j = idx - i * m;
        const float* base = sA + (f * i + o) * 128 + (f * j + o);
        sD[off + idx] = 0.25f * (base[0] + base[1] + base[128] + base[129]);
    }
    __syncthreads();

    const float bias = sMeta[0];
    for (int p = tid; p < 5376; p += 1024) {
        int m, off, idx;
        if (p < 4096)      { m = 64; off = 0;    idx = p; }
        else if (p < 5120) { m = 32; off = 4096; idx = p - 4096; }
        else               { m = 16; off = 5120; idx = p - 5120; }
        int i = idx / m, j = idx - i * m;
        float s = bias;
        const float* Dp = sD + off;
#pragma unroll
        for (int dy = -1; dy <= 1; ++dy) {
            int ii = i + dy;
            if (ii < 0 || ii >= m) continue;
#pragma unroll
            for (int dx = -1; dx <= 1; ++dx) {
                int jj = j + dx;
                if (jj < 0 || jj >= m) continue;
                s += sK[(dy + 1) * 3 + (dx + 1)] * Dp[ii * m + jj];
            }
        }
        sC[off + idx] = s;
    }
    __syncthreads();

    const float g0 = sMeta[1], g1 = sMeta[2], g2 = sMeta[3], g3 = sMeta[4];
    float* __restrict__ M = g_mixed + ch * PLANE;
#pragma unroll
    for (int it = 0; it < 4; ++it) {
        int p = q * 4096 + tid + 1024 * it;
        int i = p >> 7, j = p & 127;
        float s = bias;
#pragma unroll
        for (int dy = -1; dy <= 1; ++dy) {
            int ii = i + dy;
            if (ii < 0 || ii > 127) continue;
#pragma unroll
            for (int dx = -1; dx <= 1; ++dx) {
                int jj = j + dx;
                if (jj < 0 || jj > 127) continue;
                s += sK[(dy + 1) * 3 + (dx + 1)] * sA[ii * 128 + jj];
            }
        }
        float acc = g0 * s;
        acc += g1 * up_sample_s<1>(sC, i, j);
        acc += g2 * up_sample_s<2>(sC + 4096, i, j);
        acc += g3 * up_sample_s<3>(sC + 5120, i, j);
        M[p] = acc;
    }
}

// ============================================================
// K4: out = x + mixed @ Wu + bu. Register-invariant weights, planar
// scalar m-loads, unroll 4. (R9-proven, ~127us)
// ============================================================
__global__ __launch_bounds__(256) void k_proj_up(const float* __restrict__ x,
                                                 const float* __restrict__ Wu,
                                                 const float* __restrict__ bu,
                                                 float* __restrict__ out) {
    const int p0 = blockIdx.x * 256 + threadIdx.x;
    const int q  = p0 % 192;                  // fixed d-chunk for this thread
    const int d4 = q * 4;
    const float4 wu0 = __ldg((const float4*)(Wu + d4));
    const float4 wu1 = __ldg((const float4*)(Wu + Dd + d4));
    const float4 wu2 = __ldg((const float4*)(Wu + 2 * Dd + d4));
    const float4 bb  = __ldg((const float4*)(bu + d4));

    const int tkstep = (K4GRID * 256) / 192;  // 6312 tokens per iteration step
    const int ntok = Bb * Nn;
#pragma unroll 4
    for (int tk = p0 / 192; tk < ntok; tk += tkstep) {
        int b = tk >> 14;
        int t = tk & (Nn - 1);
        const float* mp = g_mixed + b * CHPLN + t;
        float m0 = __ldg(mp), m1 = __ldg(mp + PLANE), m2 = __ldg(mp + 2 * PLANE);
        int p = tk * 192 + q;
        float4 xv = ((const float4*)x)[p];
        float4 ov;
        ov.x = xv.x + bb.x + m0 * wu0.x + m1 * wu1.x + m2 * wu2.x;
        ov.y = xv.y + bb.y + m0 * wu0.y + m1 * wu1.y + m2 * wu2.y;
        ov.z = xv.z + bb.z + m0 * wu0.z + m1 * wu1.z + m2 * wu2.z;
        ov.w = xv.w + bb.w + m0 * wu0.w + m1 * wu1.w + m2 * wu2.w;
        ((float4*)out)[p] = ov;
    }
}

// ============================================================
// launch (3 launches)
// ============================================================
extern "C" void kernel_launch(void* const* d_in, const int* in_sizes, int n_in,
                              void* d_out, int out_size) {
    const float* x     = (const float*)d_in[0];
    const float* noise = (const float*)d_in[1];
    const float* Wd    = (const float*)d_in[2];
    const float* bd    = (const float*)d_in[3];
    const float* Wu    = (const float*)d_in[4];
    const float* bu    = (const float*)d_in[5];
    const float* Wg    = (const float*)d_in[6];
    const float* Wn    = (const float*)d_in[7];
    const float* dwk   = (const float*)d_in[8];
    const float* dwb   = (const float*)d_in[9];
    float* out = (float*)d_out;

    cudaFuncSetAttribute(k_proj_down, cudaFuncAttributeMaxDynamicSharedMemorySize, 98304);
    cudaFuncSetAttribute(k_experts,   cudaFuncAttributeMaxDynamicSharedMemorySize, 108544);

    k_proj_down<<<Bb * KBLK, 256, 98304>>>(x, Wd, bd);
    k_experts<<<dim3(4, 24), 1024, 108544>>>(dwk, dwb, noise, Wg, Wn);
    k_proj_up<<<K4GRID, 256>>>(x, Wu, bu, out);
}